// round 1
// baseline (speedup 1.0000x reference)
#include <cuda_runtime.h>

// Burden_29145648070955: strategic-training forward path.
//
// Reduction: the CCP fixed point x_{t+1} = X + 0.5*nab(x_t.w+b)*w only moves x
// along w, so s_t = x_t.w + b satisfies the SCALAR recurrence
//     s_{t+1} = (X.w + b) + 0.5*||w||^2 * nab(s_t),  nab(z)=0.5*(z+1)/sqrt((z+1)^2+1)
// and the final score X_opt.w + b is exactly s_21 (21st iterate).
// => one streaming matvec over X + per-row scalar loop. HBM-bound.

#define BATCH  65536
#define DIM    1024
#define THREADS 128
#define WARPS   (THREADS / 32)
#define ROWS_PER_WARP  32
#define ROWS_PER_BLOCK (WARPS * ROWS_PER_WARP)   // 128
#define GRID   (BATCH / ROWS_PER_BLOCK)          // 512
#define NITERS 21                                 // 20 CCP steps + final apply

__global__ void __launch_bounds__(THREADS, 1)
burden_kernel(const float* __restrict__ X,
              const float* __restrict__ w,
              const float* __restrict__ b,
              float* __restrict__ out)
{
    const int lane    = threadIdx.x & 31;
    const int warp    = threadIdx.x >> 5;
    const int rowBase = blockIdx.x * ROWS_PER_BLOCK + warp * ROWS_PER_WARP;

    // ---- w fragment in registers: lane handles float4 columns lane+32k ----
    const float4* w4p = reinterpret_cast<const float4*>(w);
    float4 w4[8];
#pragma unroll
    for (int k = 0; k < 8; k++) w4[k] = w4p[lane + 32 * k];

    // ---- ww = ||w||^2 (warp butterfly reduce, all lanes get it) ----
    float wwp = 0.f;
#pragma unroll
    for (int k = 0; k < 8; k++)
        wwp += w4[k].x * w4[k].x + w4[k].y * w4[k].y
             + w4[k].z * w4[k].z + w4[k].w * w4[k].w;
#pragma unroll
    for (int o = 16; o > 0; o >>= 1) wwp += __shfl_xor_sync(0xffffffffu, wwp, o);
    const float ww = wwp;
    const float b0 = b[0];

    // ---- 32 row-dots per warp, 2 rows in flight per step (MLP=16 LDG.128) ----
    float myS = 0.f;  // lane j ends up holding s0 for row rowBase + j
#pragma unroll 1
    for (int j = 0; j < ROWS_PER_WARP; j += 2) {
        const float4* r0 = reinterpret_cast<const float4*>(
            X + (size_t)(rowBase + j) * DIM);
        const float4* r1 = reinterpret_cast<const float4*>(
            X + (size_t)(rowBase + j + 1) * DIM);
        float a0 = 0.f, a1 = 0.f;
#pragma unroll
        for (int k = 0; k < 8; k++) {
            float4 x0 = __ldcs(&r0[lane + 32 * k]);   // stream past L2: no reuse
            float4 x1 = __ldcs(&r1[lane + 32 * k]);
            a0 += x0.x * w4[k].x + x0.y * w4[k].y + x0.z * w4[k].z + x0.w * w4[k].w;
            a1 += x1.x * w4[k].x + x1.y * w4[k].y + x1.z * w4[k].z + x1.w * w4[k].w;
        }
#pragma unroll
        for (int o = 16; o > 0; o >>= 1) {
            a0 += __shfl_xor_sync(0xffffffffu, a0, o);
            a1 += __shfl_xor_sync(0xffffffffu, a1, o);
        }
        if (lane == j)     myS = a0;
        if (lane == j + 1) myS = a1;
    }

    // ---- per-row scalar CCP recurrence, lane-parallel (row = rowBase+lane) ----
    const float t0 = myS + b0;        // s_0 = X.w + b
    const float c  = 0.5f * ww;
    float s = t0;
#pragma unroll
    for (int it = 0; it < NITERS; it++) {
        float z   = s + 1.0f;                       // slope = 1
        float nab = 0.5f * z * rsqrtf(z * z + 1.0f);
        s = t0 + c * nab;
    }
    // s_21 == X_opt.w + b == output
    out[rowBase + lane] = s;
}

extern "C" void kernel_launch(void* const* d_in, const int* in_sizes, int n_in,
                              void* d_out, int out_size)
{
    const float* X = (const float*)d_in[0];
    const float* w = (const float*)d_in[1];
    const float* b = (const float*)d_in[2];
    float* out = (float*)d_out;
    (void)in_sizes; (void)n_in; (void)out_size;

    burden_kernel<<<GRID, THREADS>>>(X, w, b, out);
}